// round 1
// baseline (speedup 1.0000x reference)
#include <cuda_runtime.h>
#include <cuda_bf16.h>
#include <cstdint>

// ClusterDiceLoss: per-cluster dice over 65-segment labels (0 = background),
// loss = 1 - mean(dice over clusters 1..K).
//
// Strategy round 1:
//   - Packed 64-bit shared-memory histogram: one atomicAdd per eligible voxel
//     carrying (sum_t | sum_p<<21 | inter<<42). Background / all-zero voxels skipped.
//   - Per-block flush to global float accumulators via atomicAdd.
//   - Tiny finalize kernel computes dice + mean.

#define NSEG 65              // K=64 clusters + background
#define ACC_N (3 * NSEG)

__device__ float g_acc[ACC_N];   // [0..64]=inter, [65..129]=sum_p, [130..194]=sum_t

__global__ void zero_acc_kernel() {
    int i = threadIdx.x;
    if (i < ACC_N) g_acc[i] = 0.0f;
}

__global__ void __launch_bounds__(256) accum_kernel(
    const float4* __restrict__ pred4,
    const float4* __restrict__ targ4,
    const int4*   __restrict__ lab4,
    long long n4,
    const float*  __restrict__ pred_s,   // scalar views for tail
    const float*  __restrict__ targ_s,
    const int*    __restrict__ lab_s,
    long long n_total)
{
    __shared__ unsigned long long s_pack[NSEG];

    int tid = threadIdx.x;
    if (tid < NSEG) s_pack[tid] = 0ULL;
    __syncthreads();

    long long stride = (long long)gridDim.x * blockDim.x;
    for (long long i = (long long)blockIdx.x * blockDim.x + tid; i < n4; i += stride) {
        int4   L = lab4[i];
        float4 P = pred4[i];
        float4 T = targ4[i];

        {
            int pp = P.x > 0.0f, tt = T.x > 0.0f;
            if (L.x > 0 && (pp | tt)) {
                unsigned long long c = (unsigned long long)tt
                                     | ((unsigned long long)pp << 21)
                                     | ((unsigned long long)(pp & tt) << 42);
                atomicAdd(&s_pack[L.x], c);
            }
        }
        {
            int pp = P.y > 0.0f, tt = T.y > 0.0f;
            if (L.y > 0 && (pp | tt)) {
                unsigned long long c = (unsigned long long)tt
                                     | ((unsigned long long)pp << 21)
                                     | ((unsigned long long)(pp & tt) << 42);
                atomicAdd(&s_pack[L.y], c);
            }
        }
        {
            int pp = P.z > 0.0f, tt = T.z > 0.0f;
            if (L.z > 0 && (pp | tt)) {
                unsigned long long c = (unsigned long long)tt
                                     | ((unsigned long long)pp << 21)
                                     | ((unsigned long long)(pp & tt) << 42);
                atomicAdd(&s_pack[L.z], c);
            }
        }
        {
            int pp = P.w > 0.0f, tt = T.w > 0.0f;
            if (L.w > 0 && (pp | tt)) {
                unsigned long long c = (unsigned long long)tt
                                     | ((unsigned long long)pp << 21)
                                     | ((unsigned long long)(pp & tt) << 42);
                atomicAdd(&s_pack[L.w], c);
            }
        }
    }

    // Tail (n_total not divisible by 4) — handled by block 0 only.
    if (blockIdx.x == 0) {
        for (long long i = n4 * 4 + tid; i < n_total; i += blockDim.x) {
            int   l  = lab_s[i];
            int pp = pred_s[i] > 0.0f, tt = targ_s[i] > 0.0f;
            if (l > 0 && (pp | tt)) {
                unsigned long long c = (unsigned long long)tt
                                     | ((unsigned long long)pp << 21)
                                     | ((unsigned long long)(pp & tt) << 42);
                atomicAdd(&s_pack[l], c);
            }
        }
    }

    __syncthreads();

    if (tid < NSEG) {
        unsigned long long v = s_pack[tid];
        if (v) {
            const unsigned long long M21 = (1ULL << 21) - 1ULL;
            float st = (float)(v & M21);
            float sp = (float)((v >> 21) & M21);
            float it = (float)(v >> 42);
            if (it > 0.0f) atomicAdd(&g_acc[tid], it);
            if (sp > 0.0f) atomicAdd(&g_acc[NSEG + tid], sp);
            if (st > 0.0f) atomicAdd(&g_acc[2 * NSEG + tid], st);
        }
    }
}

__global__ void finalize_kernel(float* __restrict__ out, const int* __restrict__ num_clusters_p) {
    __shared__ float sdice[64];
    int tid = threadIdx.x;   // 64 threads, cluster s = tid+1
    int s = tid + 1;
    float it = g_acc[s];
    float sp = g_acc[NSEG + s];
    float st = g_acc[2 * NSEG + s];
    float u  = sp + st;
    float dice = (u > 0.0f) ? (2.0f * it / fmaxf(u, 1.0f)) : 1.0f;
    sdice[tid] = dice;
    __syncthreads();
    if (tid == 0) {
        float sum = 0.0f;
        #pragma unroll
        for (int i = 0; i < 64; i++) sum += sdice[i];
        int K = *num_clusters_p;
        out[0] = 1.0f - sum / (float)K;
    }
}

extern "C" void kernel_launch(void* const* d_in, const int* in_sizes, int n_in,
                              void* d_out, int out_size) {
    const float* pred   = (const float*)d_in[0];
    const float* target = (const float*)d_in[1];
    const int*   labels = (const int*)d_in[2];
    const int*   numcl  = (const int*)d_in[3];
    float* out = (float*)d_out;

    long long n  = (long long)in_sizes[0];
    long long n4 = n >> 2;

    zero_acc_kernel<<<1, 256>>>();

    int blocks = 148 * 8;   // ~14K elements/block; packed 21-bit fields safe
    accum_kernel<<<blocks, 256>>>(
        (const float4*)pred, (const float4*)target, (const int4*)labels, n4,
        pred, target, labels, n);

    finalize_kernel<<<1, 64>>>(out, numcl);
}